// round 2
// baseline (speedup 1.0000x reference)
#include <cuda_runtime.h>
#include <math.h>

#define D 2048
#define SQ 2048
#define NB 8
#define NH 16
#define NL 2
#define DC 4096
#define IM 16384
#define PADID 50257
#define EPSLN 1e-5f
#define NLB (NL*NB)

__device__ int   g_idx[NB];
__device__ float g_lnlast[NL*NB*D];
__device__ float g_qp[16*NL*NB*D];
__device__ float g_q[NL*NB*D];
__device__ float g_r[NL*NB*D*NH];
__device__ float g_t1[NLB*NH];
__device__ float g_t2[NLB*NH];
__device__ float g_dgp[4*NLB*NH*SQ];
__device__ float g_sump[4*NLB*SQ];
__device__ float g_ssqp[4*NLB*SQ];
__device__ float g_wt[NLB*NH*SQ];
__device__ float g_W0[NLB*NH];
__device__ float g_cp[4*NLB*NH*D];
__device__ float g_c[NLB*NH*D];
__device__ float g_ofp[8*NLB*D];
__device__ float g_of[NLB*D];
__device__ float g_aop[16*NLB*D];
__device__ float g_hcat[NB*DC];
__device__ float g_z1p[8*NB*IM];
__device__ float g_z1[NB*IM];
__device__ float g_m2p[32*NB*DC];
__device__ float g_hfin[NB*DC];

#define FMA16(A,X,Q0,Q1,Q2,Q3) do{ float _x=(X); \
  A[0]+=_x*Q0.x;A[1]+=_x*Q0.y;A[2]+=_x*Q0.z;A[3]+=_x*Q0.w; \
  A[4]+=_x*Q1.x;A[5]+=_x*Q1.y;A[6]+=_x*Q1.z;A[7]+=_x*Q1.w; \
  A[8]+=_x*Q2.x;A[9]+=_x*Q2.y;A[10]+=_x*Q2.z;A[11]+=_x*Q2.w; \
  A[12]+=_x*Q3.x;A[13]+=_x*Q3.y;A[14]+=_x*Q3.z;A[15]+=_x*Q3.w; }while(0)

#define FMA8(A,W,Q0,Q1) do{ float _w=(W); \
  A[0]+=Q0.x*_w;A[1]+=Q0.y*_w;A[2]+=Q0.z*_w;A[3]+=Q0.w*_w; \
  A[4]+=Q1.x*_w;A[5]+=Q1.y*_w;A[6]+=Q1.z*_w;A[7]+=Q1.w*_w; }while(0)

// ---------- idx: last non-pad token per batch ----------
__global__ void k_idx(const int* __restrict__ ids){
  int b=blockIdx.x, t=threadIdx.x; int best=-1;
  for(int s=t;s<SQ;s+=256) if(ids[b*SQ+s]!=PADID) best=s;
  __shared__ int sm[256]; sm[t]=best; __syncthreads();
  for(int o=128;o;o>>=1){ if(t<o) sm[t]=max(sm[t],sm[t+o]); __syncthreads(); }
  if(t==0) g_idx[b]=sm[0]<0?0:sm[0];
}

// ---------- normalized last-token row ----------
__global__ void k_lnlast(const float* __restrict__ hs0,const float* __restrict__ hs1,
                         const float* __restrict__ lng,const float* __restrict__ lnb){
  int b=blockIdx.x, l=blockIdx.y, t=threadIdx.x;
  const float* x=(l?hs1:hs0)+((size_t)b*SQ+g_idx[b])*D;
  float xv[8],s1=0.f,s2=0.f;
#pragma unroll
  for(int k=0;k<8;k++){ float v=x[t+k*256]; xv[k]=v; s1+=v; s2+=v*v; }
  __shared__ float sa[256],sb[256];
  sa[t]=s1; sb[t]=s2; __syncthreads();
  for(int o=128;o;o>>=1){ if(t<o){ sa[t]+=sa[t+o]; sb[t]+=sb[t+o]; } __syncthreads(); }
  float m=sa[0]*(1.f/D), rs=rsqrtf(sb[0]*(1.f/D)-m*m+EPSLN);
  float* out=g_lnlast+(l*NB+b)*D;
#pragma unroll
  for(int k=0;k<8;k++){ int i=t+k*256; out[i]=(xv[k]-m)*rs*lng[l*D+i]+lnb[l*D+i]; }
}

// ---------- q = lnlast @ Wq (split-i partials) ----------
__global__ void k_q(const float* __restrict__ Wq){
  int t=threadIdx.x, n=blockIdx.x*256+t, sp=blockIdx.y, l=blockIdx.z;
  __shared__ float sln[128*NB];
  for(int idx=t;idx<128*NB;idx+=256){ int i=idx>>3,b=idx&7; sln[idx]=g_lnlast[(l*NB+b)*D+sp*128+i]; }
  __syncthreads();
  const float* W=Wq+(size_t)l*D*D+(size_t)sp*128*D+n;
  float acc[NB]={0};
  for(int i=0;i<128;i++){
    float w=W[(size_t)i*D];
    float4 l0=*(const float4*)&sln[i*8], l1=*(const float4*)&sln[i*8+4];
    FMA8(acc,w,l0,l1);
  }
#pragma unroll
  for(int b=0;b<NB;b++) g_qp[(size_t)((sp*NL+l)*NB+b)*D+n]=acc[b];
}
__global__ void k_qred(){
  int idx=blockIdx.x*256+threadIdx.x; if(idx>=NL*NB*D) return;
  float s=0;
#pragma unroll
  for(int sp=0;sp<16;sp++) s+=g_qp[(size_t)sp*NL*NB*D+idx];
  g_q[idx]=s;
}

// ---------- r[lb,i,h] = Wk[i,hslice] . q[hslice] ----------
__global__ void k_r(const float* __restrict__ Wk){
  int warp=threadIdx.x>>5, lane=threadIdx.x&31, l=blockIdx.y;
  int pair=blockIdx.x*8+warp, i=pair>>4, h=pair&15;
  float4 wv=*(const float4*)&Wk[(size_t)l*D*D+(size_t)i*D+h*128+lane*4];
  float a[NB];
#pragma unroll
  for(int b=0;b<NB;b++){
    float4 qv=*(const float4*)&g_q[(l*NB+b)*D+h*128+lane*4];
    a[b]=wv.x*qv.x+wv.y*qv.y+wv.z*qv.z+wv.w*qv.w;
  }
#pragma unroll
  for(int b=0;b<NB;b++)
    for(int o=16;o;o>>=1) a[b]+=__shfl_down_sync(0xffffffffu,a[b],o);
  if(lane==0){
#pragma unroll
    for(int b=0;b<NB;b++) g_r[((size_t)(l*NB+b)*D+i)*NH+h]=a[b];
  }
}

// ---------- t1 = sum_i g r ; t2 = sum_i b r ----------
__global__ void k_t(const float* __restrict__ lng,const float* __restrict__ lnb){
  int lb=blockIdx.x, t=threadIdx.x, l=lb>>3;
  float a1[16]={0},a2[16]={0};
  for(int i=t;i<D;i+=256){
    float g=lng[l*D+i], bb=lnb[l*D+i];
    const float4* rp=(const float4*)(g_r+((size_t)lb*D+i)*NH);
    float4 r0=rp[0],r1=rp[1],r2=rp[2],r3=rp[3];
    FMA16(a1,g,r0,r1,r2,r3); FMA16(a2,bb,r0,r1,r2,r3);
  }
#pragma unroll
  for(int h=0;h<16;h++)
    for(int o=16;o;o>>=1){ a1[h]+=__shfl_down_sync(~0u,a1[h],o); a2[h]+=__shfl_down_sync(~0u,a2[h],o); }
  __shared__ float s1[8][16],s2[8][16];
  int w=t>>5;
  if((t&31)==0){ for(int h=0;h<16;h++){ s1[w][h]=a1[h]; s2[w][h]=a2[h]; } }
  __syncthreads();
  if(t<16){ float x=0,y=0; for(int w2=0;w2<8;w2++){ x+=s1[w2][t]; y+=s2[w2][t]; }
    g_t1[lb*NH+t]=x; g_t2[lb*NH+t]=y; }
}

// ---------- pass1: dg[s,h], sum[s], ssq[s] over raw hs ----------
__global__ void k_pass1(const float* __restrict__ hs0,const float* __restrict__ hs1,
                        const float* __restrict__ lng){
  __shared__ float4 rs4[2048];
  int t=threadIdx.x, sp=blockIdx.x, rg=blockIdx.y, lb=blockIdx.z;
  int l=lb>>3, b=lb&7, kb=sp*512;
  const float* x=(l?hs1:hs0)+(size_t)b*SQ*D;
  const float4* rsrc=(const float4*)(g_r+((size_t)lb*D+kb)*NH);
  for(int idx=t;idx<2048;idx+=256){
    float g=lng[l*D+kb+(idx>>2)];
    float4 v=rsrc[idx]; v.x*=g; v.y*=g; v.z*=g; v.w*=g; rs4[idx]=v;
  }
  __syncthreads();
  int r0=rg*512+t, r1=r0+256;
  float a0[16]={0},a1[16]={0},s10=0,s20=0,s11=0,s21=0;
  const float4* x0=(const float4*)(x+(size_t)r0*D+kb);
  const float4* x1=(const float4*)(x+(size_t)r1*D+kb);
  for(int kk=0;kk<512;kk+=4){
    float4 xa=x0[kk>>2], xb=x1[kk>>2];
    float u4[4]={xa.x,xa.y,xa.z,xa.w}, v4[4]={xb.x,xb.y,xb.z,xb.w};
#pragma unroll
    for(int j=0;j<4;j++){
      float4 q0=rs4[(kk+j)*4],q1=rs4[(kk+j)*4+1],q2=rs4[(kk+j)*4+2],q3=rs4[(kk+j)*4+3];
      float u=u4[j], v=v4[j];
      s10+=u; s20+=u*u; s11+=v; s21+=v*v;
      FMA16(a0,u,q0,q1,q2,q3); FMA16(a1,v,q0,q1,q2,q3);
    }
  }
  size_t base=(size_t)((sp*NLB+lb)*NH)*SQ;
#pragma unroll
  for(int h=0;h<16;h++){ g_dgp[base+(size_t)h*SQ+r0]=a0[h]; g_dgp[base+(size_t)h*SQ+r1]=a1[h]; }
  g_sump[(sp*NLB+lb)*SQ+r0]=s10; g_sump[(sp*NLB+lb)*SQ+r1]=s11;
  g_ssqp[(sp*NLB+lb)*SQ+r0]=s20; g_ssqp[(sp*NLB+lb)*SQ+r1]=s21;
}

// ---------- scores + softmax -> wt = w*rstd, W0 = sum wt*m ----------
__global__ void k_soft(){
  int h=blockIdx.x, lb=blockIdx.y, t=threadIdx.x;
  float t1=g_t1[lb*NH+h], t2=g_t2[lb*NH+h];
  float sc[8],mm[8],rr[8];
#pragma unroll
  for(int k=0;k<8;k++){
    int s=t+k*256; float su=0,sq=0,dg=0;
#pragma unroll
    for(int sp=0;sp<4;sp++){
      su+=g_sump[(sp*NLB+lb)*SQ+s]; sq+=g_ssqp[(sp*NLB+lb)*SQ+s];
      dg+=g_dgp[(size_t)((sp*NLB+lb)*NH+h)*SQ+s];
    }
    float m=su*(1.f/D), var=sq*(1.f/D)-m*m, rs=rsqrtf(var+EPSLN);
    mm[k]=m; rr[k]=rs; sc[k]=rs*(dg-m*t1)+t2;
  }
  __shared__ float sm[256];
  float mx=sc[0];
#pragma unroll
  for(int k=1;k<8;k++) mx=fmaxf(mx,sc[k]);
  sm[t]=mx; __syncthreads();
  for(int o=128;o;o>>=1){ if(t<o) sm[t]=fmaxf(sm[t],sm[t+o]); __syncthreads(); }
  mx=sm[0]; __syncthreads();
  float e[8],es=0;
#pragma unroll
  for(int k=0;k<8;k++){ e[k]=expf(sc[k]-mx); es+=e[k]; }
  sm[t]=es; __syncthreads();
  for(int o=128;o;o>>=1){ if(t<o) sm[t]+=sm[t+o]; __syncthreads(); }
  float inv=1.f/sm[0]; __syncthreads();
  float w0=0;
#pragma unroll
  for(int k=0;k<8;k++){
    float wt=e[k]*inv*rr[k];
    g_wt[(size_t)(lb*NH+h)*SQ+t+k*256]=wt; w0+=wt*mm[k];
  }
  sm[t]=w0; __syncthreads();
  for(int o=128;o;o>>=1){ if(t<o) sm[t]+=sm[t+o]; __syncthreads(); }
  if(t==0) g_W0[lb*NH+h]=sm[0];
}

// ---------- pass2: craw[h,d] = sum_s wt[h,s] x[s,d] ----------
__global__ void k_pass2(const float* __restrict__ hs0,const float* __restrict__ hs1){
  __shared__ float swt[512*16];
  int t=threadIdx.x, sp=blockIdx.x, cg=blockIdx.y, lb=blockIdx.z;
  int l=lb>>3, b=lb&7, sb=sp*512;
  for(int h=0;h<16;h++)
    for(int s=t;s<512;s+=256) swt[s*16+h]=g_wt[(size_t)(lb*NH+h)*SQ+sb+s];
  __syncthreads();
  const float* x=(l?hs1:hs0)+(size_t)b*SQ*D;
  int c0=cg*512+t, c1=c0+256;
  float a0[16]={0},a1[16]={0};
  for(int s=0;s<512;s++){
    float u=x[(size_t)(sb+s)*D+c0], v=x[(size_t)(sb+s)*D+c1];
    float4 q0=*(const float4*)&swt[s*16],q1=*(const float4*)&swt[s*16+4];
    float4 q2=*(const float4*)&swt[s*16+8],q3=*(const float4*)&swt[s*16+12];
    FMA16(a0,u,q0,q1,q2,q3); FMA16(a1,v,q0,q1,q2,q3);
  }
  size_t base=(size_t)((sp*NLB+lb)*NH)*D;
#pragma unroll
  for(int h=0;h<16;h++){ g_cp[base+(size_t)h*D+c0]=a0[h]; g_cp[base+(size_t)h*D+c1]=a1[h]; }
}

// ---------- finalize c = g*(sum - W0) + b ----------
__global__ void k_cred(const float* __restrict__ lng,const float* __restrict__ lnb){
  int idx=blockIdx.x*256+threadIdx.x; if(idx>=NLB*NH*D) return;
  int d=idx&(D-1), h=(idx>>11)&15, lb=idx>>15, l=lb>>3;
  float s=0;
#pragma unroll
  for(int sp=0;sp<4;sp++) s+=g_cp[(size_t)((sp*NLB+lb)*NH+h)*D+d];
  g_c[idx]=lng[l*D+d]*(s-g_W0[lb*NH+h])+lnb[l*D+d];
}

// ---------- oflat[m] = sum_d c[h,d] Wv[d,m] ----------
__global__ void k_of(const float* __restrict__ Wv){
  __shared__ float sc[256*8];
  int t=threadIdx.x, h=blockIdx.x, sp=blockIdx.y, l=blockIdx.z, db=sp*256;
  for(int idx=t;idx<256*8;idx+=128){ int d=idx>>3,b=idx&7;
    sc[idx]=g_c[(size_t)((l*8+b)*NH+h)*D+db+d]; }
  __syncthreads();
  const float* W=Wv+(size_t)l*D*D+(size_t)db*D+h*128+t;
  float acc[NB]={0};
  for(int d=0;d<256;d++){
    float w=W[(size_t)d*D];
    float4 c0=*(const float4*)&sc[d*8],c1=*(const float4*)&sc[d*8+4];
    FMA8(acc,w,c0,c1);
  }
#pragma unroll
  for(int b=0;b<NB;b++) g_ofp[(size_t)((sp*NL+l)*NB+b)*D+h*128+t]=acc[b];
}
__global__ void k_ofred(){
  int idx=blockIdx.x*256+threadIdx.x; if(idx>=NLB*D) return;
  float s=0;
#pragma unroll
  for(int sp=0;sp<8;sp++) s+=g_ofp[(size_t)sp*NLB*D+idx];
  g_of[idx]=s;
}

// ---------- attnout = of @ Wo -> hcat ----------
__global__ void k_ao(const float* __restrict__ Wo){
  __shared__ float sof[128*8];
  int t=threadIdx.x, cb=blockIdx.x, sp=blockIdx.y, l=blockIdx.z, mb=sp*128, n=cb*256+t;
  for(int idx=t;idx<128*8;idx+=256){ int m=idx>>3,b=idx&7; sof[idx]=g_of[(l*8+b)*D+mb+m]; }
  __syncthreads();
  const float* W=Wo+(size_t)l*D*D+(size_t)mb*D+n;
  float acc[NB]={0};
  for(int m=0;m<128;m++){
    float w=W[(size_t)m*D];
    float4 o0=*(const float4*)&sof[m*8],o1=*(const float4*)&sof[m*8+4];
    FMA8(acc,w,o0,o1);
  }
#pragma unroll
  for(int b=0;b<NB;b++) g_aop[(size_t)((sp*NL+l)*NB+b)*D+n]=acc[b];
}
__global__ void k_aored(const float* __restrict__ bo){
  int idx=blockIdx.x*256+threadIdx.x; if(idx>=NLB*D) return;
  int n=idx&(D-1), lb=idx>>11, l=lb>>3, b=lb&7;
  float s=0;
#pragma unroll
  for(int sp=0;sp<16;sp++) s+=g_aop[(size_t)sp*NLB*D+idx];
  g_hcat[b*DC+l*D+n]=s+bo[l*D+n];
}

// ---------- MLP layer 1 ----------
__global__ void k_m1(const float* __restrict__ W1){
  __shared__ float sh[512*8];
  int t=threadIdx.x, p=blockIdx.x*256+t, cb=blockIdx.y*512;
  for(int idx=t;idx<512*8;idx+=256){ int c=idx>>3,b=idx&7; sh[idx]=g_hcat[b*DC+cb+c]; }
  __syncthreads();
  const float* W=W1+(size_t)cb*IM+p;
  float acc[NB]={0};
  for(int c=0;c<512;c++){
    float w=W[(size_t)c*IM];
    float4 h0=*(const float4*)&sh[c*8],h1=*(const float4*)&sh[c*8+4];
    FMA8(acc,w,h0,h1);
  }
#pragma unroll
  for(int b=0;b<NB;b++) g_z1p[(size_t)(blockIdx.y*NB+b)*IM+p]=acc[b];
}
__global__ void k_z1red(const float* __restrict__ b1){
  int idx=blockIdx.x*256+threadIdx.x; if(idx>=NB*IM) return;
  int p=idx&(IM-1);
  float s=b1[p];
#pragma unroll
  for(int sp=0;sp<8;sp++) s+=g_z1p[(size_t)sp*NB*IM+idx];
  g_z1[idx]=0.5f*s*(1.0f+erff(s*0.70710678118654752f));
}

// ---------- MLP layer 2 + residual ----------
__global__ void k_m2(const float* __restrict__ W2){
  __shared__ float sz[512*8];
  int t=threadIdx.x, c=blockIdx.x*256+t, pb=blockIdx.y*512;
  for(int idx=t;idx<512*8;idx+=256){ int p=idx>>3,b=idx&7; sz[idx]=g_z1[b*IM+pb+p]; }
  __syncthreads();
  const float* W=W2+(size_t)pb*DC+c;
  float acc[NB]={0};
  for(int p=0;p<512;p++){
    float w=W[(size_t)p*DC];
    float4 z0=*(const float4*)&sz[p*8],z1v=*(const float4*)&sz[p*8+4];
    FMA8(acc,w,z0,z1v);
  }
#pragma unroll
  for(int b=0;b<NB;b++) g_m2p[(size_t)(blockIdx.y*NB+b)*DC+c]=acc[b];
}
__global__ void k_m2red(const float* __restrict__ b2){
  int idx=blockIdx.x*256+threadIdx.x; if(idx>=NB*DC) return;
  int c=idx&(DC-1);
  float s=b2[c];
#pragma unroll
  for(int sp=0;sp<32;sp++) s+=g_m2p[(size_t)sp*NB*DC+idx];
  g_hfin[idx]=g_hcat[idx]+s;
}

// ---------- final logits ----------
__global__ void k_out(const float* __restrict__ Wl,const float* __restrict__ bl,
                      float* __restrict__ out){
  int b=blockIdx.x, t=threadIdx.x;
  float a0=0,a1=0;
  for(int c=t;c<DC;c+=256){
    float h=g_hfin[b*DC+c];
    a0+=h*Wl[c*2]; a1+=h*Wl[c*2+1];
  }
  __shared__ float s0[256],s1[256];
  s0[t]=a0; s1[t]=a1; __syncthreads();
  for(int o=128;o;o>>=1){ if(t<o){ s0[t]+=s0[t+o]; s1[t]+=s1[t+o]; } __syncthreads(); }
  if(t==0){ out[b*2]=s0[0]+bl[0]; out[b*2+1]=s1[0]+bl[1]; }
}

extern "C" void kernel_launch(void* const* d_in, const int* in_sizes, int n_in,
                              void* d_out, int out_size){
  const float* hs0=(const float*)d_in[0];
  const float* hs1=(const float*)d_in[1];
  const int*   ids=(const int*)d_in[2];
  const float* lng=(const float*)d_in[3];
  const float* lnb=(const float*)d_in[4];
  const float* Wq =(const float*)d_in[5];
  const float* Wk =(const float*)d_in[6];
  const float* Wv =(const float*)d_in[7];
  const float* Wo =(const float*)d_in[8];
  const float* bo =(const float*)d_in[9];
  const float* W1 =(const float*)d_in[10];
  const float* b1 =(const float*)d_in[11];
  const float* W2 =(const float*)d_in[12];
  const float* b2 =(const float*)d_in[13];
  const float* Wl =(const float*)d_in[14];
  const float* bl =(const float*)d_in[15];
  float* out=(float*)d_out;

  k_idx<<<NB,256>>>(ids);
  k_lnlast<<<dim3(NB,NL),256>>>(hs0,hs1,lng,lnb);
  k_q<<<dim3(8,16,NL),256>>>(Wq);
  k_qred<<<(NL*NB*D)/256,256>>>();
  k_r<<<dim3(D*NH/8,NL),256>>>(Wk);
  k_t<<<NLB,256>>>(lng,lnb);
  k_pass1<<<dim3(4,4,NLB),256>>>(hs0,hs1,lng);
  k_soft<<<dim3(NH,NLB),256>>>();
  k_pass2<<<dim3(4,4,NLB),256>>>(hs0,hs1);
  k_cred<<<(NLB*NH*D)/256,256>>>(lng,lnb);
  k_of<<<dim3(16,8,NL),128>>>(Wv);
  k_ofred<<<(NLB*D)/256,256>>>();
  k_ao<<<dim3(8,16,NL),256>>>(Wo);
  k_aored<<<(NLB*D)/256,256>>>(bo);
  k_m1<<<dim3(IM/256,8),256>>>(W1);
  k_z1red<<<(NB*IM)/256,256>>>(b1);
  k_m2<<<dim3(DC/256,32),256>>>(W2);
  k_m2red<<<(NB*DC)/256,256>>>(b2);
  k_out<<<NB,256>>>(Wl,bl,out);
}

// round 3
// speedup vs baseline: 1.0200x; 1.0200x over previous
#include <cuda_runtime.h>
#include <math.h>

#define D 2048
#define SQ 2048
#define NB 8
#define NH 16
#define NL 2
#define DC 4096
#define IM 16384
#define PADID 50257
#define EPSLN 1e-5f
#define NLB (NL*NB)

__device__ int   g_idx[NB];
__device__ float g_lnlast[NL*NB*D];
__device__ float g_qp[16*NL*NB*D];
__device__ float g_q[NL*NB*D];
__device__ float g_r[NL*NB*D*NH];
__device__ float g_t1[NLB*NH];
__device__ float g_t2[NLB*NH];
__device__ float g_dgp[4*NLB*NH*SQ];
__device__ float g_sump[4*NLB*SQ];
__device__ float g_ssqp[4*NLB*SQ];
__device__ float g_wt[NLB*NH*SQ];
__device__ float g_W0[NLB*NH];
__device__ float g_cp[4*NLB*NH*D];
__device__ float g_c[NLB*NH*D];
__device__ float g_ofp[8*NLB*D];
__device__ float g_of[NLB*D];
__device__ float g_aop[16*NLB*D];
__device__ float g_hcat[NB*DC];
__device__ float g_z1p[16*NB*IM];
__device__ float g_z1[NB*IM];
__device__ float g_m2p[64*NB*DC];
__device__ float g_hfin[NB*DC];

#define FMA16(A,X,Q0,Q1,Q2,Q3) do{ float _x=(X); \
  A[0]+=_x*Q0.x;A[1]+=_x*Q0.y;A[2]+=_x*Q0.z;A[3]+=_x*Q0.w; \
  A[4]+=_x*Q1.x;A[5]+=_x*Q1.y;A[6]+=_x*Q1.z;A[7]+=_x*Q1.w; \
  A[8]+=_x*Q2.x;A[9]+=_x*Q2.y;A[10]+=_x*Q2.z;A[11]+=_x*Q2.w; \
  A[12]+=_x*Q3.x;A[13]+=_x*Q3.y;A[14]+=_x*Q3.z;A[15]+=_x*Q3.w; }while(0)

#define FMA8(A,W,Q0,Q1) do{ float _w=(W); \
  A[0]+=Q0.x*_w;A[1]+=Q0.y*_w;A[2]+=Q0.z*_w;A[3]+=Q0.w*_w; \
  A[4]+=Q1.x*_w;A[5]+=Q1.y*_w;A[6]+=Q1.z*_w;A[7]+=Q1.w*_w; }while(0)

// ---------- idx: last non-pad token per batch ----------
__global__ void k_idx(const int* __restrict__ ids){
  int b=blockIdx.x, t=threadIdx.x; int best=-1;
  for(int s=t;s<SQ;s+=256) if(ids[b*SQ+s]!=PADID) best=s;
  __shared__ int sm[256]; sm[t]=best; __syncthreads();
  for(int o=128;o;o>>=1){ if(t<o) sm[t]=max(sm[t],sm[t+o]); __syncthreads(); }
  if(t==0) g_idx[b]=sm[0]<0?0:sm[0];
}

// ---------- normalized last-token row ----------
__global__ void k_lnlast(const float* __restrict__ hs0,const float* __restrict__ hs1,
                         const float* __restrict__ lng,const float* __restrict__ lnb){
  int b=blockIdx.x, l=blockIdx.y, t=threadIdx.x;
  const float* x=(l?hs1:hs0)+((size_t)b*SQ+g_idx[b])*D;
  float xv[8],s1=0.f,s2=0.f;
#pragma unroll
  for(int k=0;k<8;k++){ float v=x[t+k*256]; xv[k]=v; s1+=v; s2+=v*v; }
  __shared__ float sa[256],sb[256];
  sa[t]=s1; sb[t]=s2; __syncthreads();
  for(int o=128;o;o>>=1){ if(t<o){ sa[t]+=sa[t+o]; sb[t]+=sb[t+o]; } __syncthreads(); }
  float m=sa[0]*(1.f/D), rs=rsqrtf(sb[0]*(1.f/D)-m*m+EPSLN);
  float* out=g_lnlast+(l*NB+b)*D;
#pragma unroll
  for(int k=0;k<8;k++){ int i=t+k*256; out[i]=(xv[k]-m)*rs*lng[l*D+i]+lnb[l*D+i]; }
}

// ---------- q = lnlast @ Wq (split-i partials) ----------
__global__ void k_q(const float* __restrict__ Wq){
  int t=threadIdx.x, n=blockIdx.x*256+t, sp=blockIdx.y, l=blockIdx.z;
  __shared__ float sln[128*NB];
  for(int idx=t;idx<128*NB;idx+=256){ int i=idx>>3,b=idx&7; sln[idx]=g_lnlast[(l*NB+b)*D+sp*128+i]; }
  __syncthreads();
  const float* W=Wq+(size_t)l*D*D+(size_t)sp*128*D+n;
  float acc[NB]={0};
#pragma unroll 8
  for(int i=0;i<128;i++){
    float w=W[(size_t)i*D];
    float4 l0=*(const float4*)&sln[i*8], l1=*(const float4*)&sln[i*8+4];
    FMA8(acc,w,l0,l1);
  }
#pragma unroll
  for(int b=0;b<NB;b++) g_qp[(size_t)((sp*NL+l)*NB+b)*D+n]=acc[b];
}
__global__ void k_qred(){
  int idx=blockIdx.x*256+threadIdx.x; if(idx>=NL*NB*D) return;
  float s=0;
#pragma unroll
  for(int sp=0;sp<16;sp++) s+=g_qp[(size_t)sp*NL*NB*D+idx];
  g_q[idx]=s;
}

// ---------- r[lb,i,h] = Wk[i,hslice] . q[hslice] ----------
__global__ void k_r(const float* __restrict__ Wk){
  int warp=threadIdx.x>>5, lane=threadIdx.x&31, l=blockIdx.y;
  int pair=blockIdx.x*8+warp, i=pair>>4, h=pair&15;
  float4 wv=*(const float4*)&Wk[(size_t)l*D*D+(size_t)i*D+h*128+lane*4];
  float a[NB];
#pragma unroll
  for(int b=0;b<NB;b++){
    float4 qv=*(const float4*)&g_q[(l*NB+b)*D+h*128+lane*4];
    a[b]=wv.x*qv.x+wv.y*qv.y+wv.z*qv.z+wv.w*qv.w;
  }
#pragma unroll
  for(int b=0;b<NB;b++)
    for(int o=16;o;o>>=1) a[b]+=__shfl_down_sync(0xffffffffu,a[b],o);
  if(lane==0){
#pragma unroll
    for(int b=0;b<NB;b++) g_r[((size_t)(l*NB+b)*D+i)*NH+h]=a[b];
  }
}

// ---------- t1 = sum_i g r ; t2 = sum_i b r ----------
__global__ void k_t(const float* __restrict__ lng,const float* __restrict__ lnb){
  int lb=blockIdx.x, t=threadIdx.x, l=lb>>3;
  float a1[16]={0},a2[16]={0};
  for(int i=t;i<D;i+=256){
    float g=lng[l*D+i], bb=lnb[l*D+i];
    const float4* rp=(const float4*)(g_r+((size_t)lb*D+i)*NH);
    float4 r0=rp[0],r1=rp[1],r2=rp[2],r3=rp[3];
    FMA16(a1,g,r0,r1,r2,r3); FMA16(a2,bb,r0,r1,r2,r3);
  }
#pragma unroll
  for(int h=0;h<16;h++)
    for(int o=16;o;o>>=1){ a1[h]+=__shfl_down_sync(~0u,a1[h],o); a2[h]+=__shfl_down_sync(~0u,a2[h],o); }
  __shared__ float s1[8][16],s2[8][16];
  int w=t>>5;
  if((t&31)==0){ for(int h=0;h<16;h++){ s1[w][h]=a1[h]; s2[w][h]=a2[h]; } }
  __syncthreads();
  if(t<16){ float x=0,y=0; for(int w2=0;w2<8;w2++){ x+=s1[w2][t]; y+=s2[w2][t]; }
    g_t1[lb*NH+t]=x; g_t2[lb*NH+t]=y; }
}

// ---------- pass1: dg[s,h], sum[s], ssq[s] over raw hs (batched loads) ----------
__global__ void k_pass1(const float* __restrict__ hs0,const float* __restrict__ hs1,
                        const float* __restrict__ lng){
  __shared__ float4 rs4[2048];
  int t=threadIdx.x, sp=blockIdx.x, rg=blockIdx.y, lb=blockIdx.z;
  int l=lb>>3, b=lb&7, kb=sp*512;
  const float* x=(l?hs1:hs0)+(size_t)b*SQ*D;
  const float4* rsrc=(const float4*)(g_r+((size_t)lb*D+kb)*NH);
  for(int idx=t;idx<2048;idx+=256){
    float g=lng[l*D+kb+(idx>>2)];
    float4 v=rsrc[idx]; v.x*=g; v.y*=g; v.z*=g; v.w*=g; rs4[idx]=v;
  }
  __syncthreads();
  int r0=rg*512+t, r1=r0+256;
  float a0[16]={0},a1[16]={0},s10=0,s20=0,s11=0,s21=0;
  const float4* x0=(const float4*)(x+(size_t)r0*D+kb);
  const float4* x1=(const float4*)(x+(size_t)r1*D+kb);
  for(int kk=0;kk<512;kk+=16){
    float4 xa[4],xb[4];
#pragma unroll
    for(int j=0;j<4;j++){ xa[j]=x0[(kk>>2)+j]; xb[j]=x1[(kk>>2)+j]; }
    const float* ua=(const float*)xa; const float* vb=(const float*)xb;
#pragma unroll
    for(int j=0;j<16;j++){
      float4 q0=rs4[(kk+j)*4],q1=rs4[(kk+j)*4+1],q2=rs4[(kk+j)*4+2],q3=rs4[(kk+j)*4+3];
      float u=ua[j], v=vb[j];
      s10+=u; s20+=u*u; s11+=v; s21+=v*v;
      FMA16(a0,u,q0,q1,q2,q3); FMA16(a1,v,q0,q1,q2,q3);
    }
  }
  size_t base=(size_t)((sp*NLB+lb)*NH)*SQ;
#pragma unroll
  for(int h=0;h<16;h++){ g_dgp[base+(size_t)h*SQ+r0]=a0[h]; g_dgp[base+(size_t)h*SQ+r1]=a1[h]; }
  g_sump[(sp*NLB+lb)*SQ+r0]=s10; g_sump[(sp*NLB+lb)*SQ+r1]=s11;
  g_ssqp[(sp*NLB+lb)*SQ+r0]=s20; g_ssqp[(sp*NLB+lb)*SQ+r1]=s21;
}

// ---------- scores + softmax -> wt = w*rstd, W0 = sum wt*m ----------
__global__ void k_soft(){
  int h=blockIdx.x, lb=blockIdx.y, t=threadIdx.x;
  float t1=g_t1[lb*NH+h], t2=g_t2[lb*NH+h];
  float sc[8],mm[8],rr[8];
#pragma unroll
  for(int k=0;k<8;k++){
    int s=t+k*256; float su=0,sq=0,dg=0;
#pragma unroll
    for(int sp=0;sp<4;sp++){
      su+=g_sump[(sp*NLB+lb)*SQ+s]; sq+=g_ssqp[(sp*NLB+lb)*SQ+s];
      dg+=g_dgp[(size_t)((sp*NLB+lb)*NH+h)*SQ+s];
    }
    float m=su*(1.f/D), var=sq*(1.f/D)-m*m, rs=rsqrtf(var+EPSLN);
    mm[k]=m; rr[k]=rs; sc[k]=rs*(dg-m*t1)+t2;
  }
  __shared__ float sm[256];
  float mx=sc[0];
#pragma unroll
  for(int k=1;k<8;k++) mx=fmaxf(mx,sc[k]);
  sm[t]=mx; __syncthreads();
  for(int o=128;o;o>>=1){ if(t<o) sm[t]=fmaxf(sm[t],sm[t+o]); __syncthreads(); }
  mx=sm[0]; __syncthreads();
  float e[8],es=0;
#pragma unroll
  for(int k=0;k<8;k++){ e[k]=expf(sc[k]-mx); es+=e[k]; }
  sm[t]=es; __syncthreads();
  for(int o=128;o;o>>=1){ if(t<o) sm[t]+=sm[t+o]; __syncthreads(); }
  float inv=1.f/sm[0]; __syncthreads();
  float w0=0;
#pragma unroll
  for(int k=0;k<8;k++){
    float wt=e[k]*inv*rr[k];
    g_wt[(size_t)(lb*NH+h)*SQ+t+k*256]=wt; w0+=wt*mm[k];
  }
  sm[t]=w0; __syncthreads();
  for(int o=128;o;o>>=1){ if(t<o) sm[t]+=sm[t+o]; __syncthreads(); }
  if(t==0) g_W0[lb*NH+h]=sm[0];
}

// ---------- pass2: craw[h,d] = sum_s wt[h,s] x[s,d] (float2 cols, batched s) ----------
__global__ void k_pass2(const float* __restrict__ hs0,const float* __restrict__ hs1){
  __shared__ float swt[512*16];
  int t=threadIdx.x, sp=blockIdx.x, cg=blockIdx.y, lb=blockIdx.z;
  int l=lb>>3, b=lb&7, sb=sp*512;
  for(int h=0;h<16;h++)
    for(int s=t;s<512;s+=256) swt[s*16+h]=g_wt[(size_t)(lb*NH+h)*SQ+sb+s];
  __syncthreads();
  const float* x=(l?hs1:hs0)+(size_t)b*SQ*D;
  int c=cg*512+t*2;
  float a0[16]={0},a1[16]={0};
  for(int s=0;s<512;s+=8){
    float2 xv[8];
#pragma unroll
    for(int j=0;j<8;j++) xv[j]=*(const float2*)&x[(size_t)(sb+s+j)*D+c];
#pragma unroll
    for(int j=0;j<8;j++){
      float4 q0=*(const float4*)&swt[(s+j)*16],q1=*(const float4*)&swt[(s+j)*16+4];
      float4 q2=*(const float4*)&swt[(s+j)*16+8],q3=*(const float4*)&swt[(s+j)*16+12];
      FMA16(a0,xv[j].x,q0,q1,q2,q3); FMA16(a1,xv[j].y,q0,q1,q2,q3);
    }
  }
  size_t base=(size_t)((sp*NLB+lb)*NH)*D;
#pragma unroll
  for(int h=0;h<16;h++){
    float2 st; st.x=a0[h]; st.y=a1[h];
    *(float2*)&g_cp[base+(size_t)h*D+c]=st;
  }
}

// ---------- finalize c = g*(sum - W0) + b ----------
__global__ void k_cred(const float* __restrict__ lng,const float* __restrict__ lnb){
  int idx=blockIdx.x*256+threadIdx.x; if(idx>=NLB*NH*D) return;
  int d=idx&(D-1), h=(idx>>11)&15, lb=idx>>15, l=lb>>3;
  float s=0;
#pragma unroll
  for(int sp=0;sp<4;sp++) s+=g_cp[(size_t)((sp*NLB+lb)*NH+h)*D+d];
  g_c[idx]=lng[l*D+d]*(s-g_W0[lb*NH+h])+lnb[l*D+d];
}

// ---------- oflat[m] = sum_d c[h,d] Wv[d,m] ----------
__global__ void k_of(const float* __restrict__ Wv){
  __shared__ float sc[256*8];
  int t=threadIdx.x, h=blockIdx.x, sp=blockIdx.y, l=blockIdx.z, db=sp*256;
  for(int idx=t;idx<256*8;idx+=128){ int d=idx>>3,b=idx&7;
    sc[idx]=g_c[(size_t)((l*8+b)*NH+h)*D+db+d]; }
  __syncthreads();
  const float* W=Wv+(size_t)l*D*D+(size_t)db*D+h*128+t;
  float acc[NB]={0};
#pragma unroll 8
  for(int d=0;d<256;d++){
    float w=W[(size_t)d*D];
    float4 c0=*(const float4*)&sc[d*8],c1=*(const float4*)&sc[d*8+4];
    FMA8(acc,w,c0,c1);
  }
#pragma unroll
  for(int b=0;b<NB;b++) g_ofp[(size_t)((sp*NL+l)*NB+b)*D+h*128+t]=acc[b];
}
__global__ void k_ofred(){
  int idx=blockIdx.x*256+threadIdx.x; if(idx>=NLB*D) return;
  float s=0;
#pragma unroll
  for(int sp=0;sp<8;sp++) s+=g_ofp[(size_t)sp*NLB*D+idx];
  g_of[idx]=s;
}

// ---------- attnout = of @ Wo -> hcat ----------
__global__ void k_ao(const float* __restrict__ Wo){
  __shared__ float sof[128*8];
  int t=threadIdx.x, cb=blockIdx.x, sp=blockIdx.y, l=blockIdx.z, mb=sp*128, n=cb*256+t;
  for(int idx=t;idx<128*8;idx+=256){ int m=idx>>3,b=idx&7; sof[idx]=g_of[(l*8+b)*D+mb+m]; }
  __syncthreads();
  const float* W=Wo+(size_t)l*D*D+(size_t)mb*D+n;
  float acc[NB]={0};
#pragma unroll 8
  for(int m=0;m<128;m++){
    float w=W[(size_t)m*D];
    float4 o0=*(const float4*)&sof[m*8],o1=*(const float4*)&sof[m*8+4];
    FMA8(acc,w,o0,o1);
  }
#pragma unroll
  for(int b=0;b<NB;b++) g_aop[(size_t)((sp*NL+l)*NB+b)*D+n]=acc[b];
}
__global__ void k_aored(const float* __restrict__ bo){
  int idx=blockIdx.x*256+threadIdx.x; if(idx>=NLB*D) return;
  int n=idx&(D-1), lb=idx>>11, l=lb>>3, b=lb&7;
  float s=0;
#pragma unroll
  for(int sp=0;sp<16;sp++) s+=g_aop[(size_t)sp*NLB*D+idx];
  g_hcat[b*DC+l*D+n]=s+bo[l*D+n];
}

// ---------- MLP layer 1 (float4 outputs, batched weight loads) ----------
__global__ void k_m1(const float* __restrict__ W1){
  __shared__ float sh[256*8];
  int t=threadIdx.x, p=blockIdx.x*1024+t*4, cb=blockIdx.y*256;
  for(int idx=t;idx<256*8;idx+=256){ int c=idx>>3,b=idx&7; sh[idx]=g_hcat[b*DC+cb+c]; }
  __syncthreads();
  const float* W=W1+(size_t)cb*IM+p;
  float acc[8][4]={};
#pragma unroll 8
  for(int c=0;c<256;c++){
    float4 w=*(const float4*)&W[(size_t)c*IM];
    float4 h0=*(const float4*)&sh[c*8], h1=*(const float4*)&sh[c*8+4];
    float hb[8]={h0.x,h0.y,h0.z,h0.w,h1.x,h1.y,h1.z,h1.w};
#pragma unroll
    for(int b=0;b<8;b++){
      acc[b][0]+=hb[b]*w.x; acc[b][1]+=hb[b]*w.y;
      acc[b][2]+=hb[b]*w.z; acc[b][3]+=hb[b]*w.w;
    }
  }
#pragma unroll
  for(int b=0;b<8;b++) *(float4*)&g_z1p[(size_t)(blockIdx.y*NB+b)*IM+p]=*(float4*)acc[b];
}
__global__ void k_z1red(const float* __restrict__ b1){
  int idx=blockIdx.x*256+threadIdx.x; if(idx>=NB*IM) return;
  int p=idx&(IM-1);
  float s=b1[p];
#pragma unroll
  for(int sp=0;sp<16;sp++) s+=g_z1p[(size_t)sp*NB*IM+idx];
  g_z1[idx]=0.5f*s*(1.0f+erff(s*0.70710678118654752f));
}

// ---------- MLP layer 2 (float4 outputs, batched weight loads) ----------
__global__ void k_m2(const float* __restrict__ W2){
  __shared__ float sz[256*8];
  int t=threadIdx.x, c=blockIdx.x*1024+t*4, pb=blockIdx.y*256;
  for(int idx=t;idx<256*8;idx+=256){ int pp=idx>>3,b=idx&7; sz[idx]=g_z1[b*IM+pb+pp]; }
  __syncthreads();
  const float* W=W2+(size_t)pb*DC+c;
  float acc[8][4]={};
#pragma unroll 8
  for(int pp=0;pp<256;pp++){
    float4 w=*(const float4*)&W[(size_t)pp*DC];
    float4 z0=*(const float4*)&sz[pp*8], z1v=*(const float4*)&sz[pp*8+4];
    float zb[8]={z0.x,z0.y,z0.z,z0.w,z1v.x,z1v.y,z1v.z,z1v.w};
#pragma unroll
    for(int b=0;b<8;b++){
      acc[b][0]+=zb[b]*w.x; acc[b][1]+=zb[b]*w.y;
      acc[b][2]+=zb[b]*w.z; acc[b][3]+=zb[b]*w.w;
    }
  }
#pragma unroll
  for(int b=0;b<8;b++) *(float4*)&g_m2p[(size_t)(blockIdx.y*NB+b)*DC+c]=*(float4*)acc[b];
}
__global__ void k_m2red(const float* __restrict__ b2){
  int idx=blockIdx.x*256+threadIdx.x; if(idx>=NB*DC) return;
  int c=idx&(DC-1);
  float s=b2[c];
#pragma unroll
  for(int sp=0;sp<64;sp++) s+=g_m2p[(size_t)sp*NB*DC+idx];
  g_hfin[idx]=g_hcat[idx]+s;
}

// ---------- final logits ----------
__global__ void k_out(const float* __restrict__ Wl,const float* __restrict__ bl,
                      float* __restrict__ out){
  int b=blockIdx.x, t=threadIdx.x;
  float a0=0,a1=0;
  for(int c=t;c<DC;c+=256){
    float h=g_hfin[b*DC+c];
    a0+=h*Wl[c*2]; a1+=h*Wl[c*2+1];
  }
  __shared__ float s0[256],s1[256];
  s0[t]=a0; s1[t]=a1; __syncthreads();
  for(int o=128;o;o>>=1){ if(t<o){ s0[t]+=s0[t+o]; s1[t]+=s1[t+o]; } __syncthreads(); }
  if(t==0){ out[b*2]=s0[0]+bl[0]; out[b*2+1]=s1[0]+bl[1]; }
}

extern "C" void kernel_launch(void* const* d_in, const int* in_sizes, int n_in,
                              void* d_out, int out_size){
  const float* hs0=(const float*)d_in[0];
  const float* hs1=(const float*)d_in[1];
  const int*   ids=(const int*)d_in[2];
  const float* lng=(const float*)d_in[3];
  const float* lnb=(const float*)d_in[4];
  const float* Wq =(const float*)d_in[5];
  const float* Wk =(const float*)d_in[6];
  const float* Wv =(const float*)d_in[7];
  const float* Wo =(const float*)d_in[8];
  const float* bo =(const float*)d_in[9];
  const float* W1 =(const float*)d_in[10];
  const float* b1 =(const float*)d_in[11];
  const float* W2 =(const float*)d_in[12];
  const float* b2 =(const float*)d_in[13];
  const float* Wl =(const float*)d_in[14];
  const float* bl =(const float*)d_in[15];
  float* out=(float*)d_out;

  k_idx<<<NB,256>>>(ids);
  k_lnlast<<<dim3(NB,NL),256>>>(hs0,hs1,lng,lnb);
  k_q<<<dim3(8,16,NL),256>>>(Wq);
  k_qred<<<(NL*NB*D)/256,256>>>();
  k_r<<<dim3(D*NH/8,NL),256>>>(Wk);
  k_t<<<NLB,256>>>(lng,lnb);
  k_pass1<<<dim3(4,4,NLB),256>>>(hs0,hs1,lng);
  k_soft<<<dim3(NH,NLB),256>>>();
  k_pass2<<<dim3(4,4,NLB),256>>>(hs0,hs1);
  k_cred<<<(NLB*NH*D)/256,256>>>(lng,lnb);
  k_of<<<dim3(16,8,NL),128>>>(Wv);
  k_ofred<<<(NLB*D)/256,256>>>();
  k_ao<<<dim3(8,16,NL),256>>>(Wo);
  k_aored<<<(NLB*D)/256,256>>>(bo);
  k_m1<<<dim3(IM/1024,16),256>>>(W1);
  k_z1red<<<(NB*IM)/256,256>>>(b1);
  k_m2<<<dim3(DC/1024,64),256>>>(W2);
  k_m2red<<<(NB*DC)/256,256>>>(b2);
  k_out<<<NB,256>>>(Wl,bl,out);
}

// round 5
// speedup vs baseline: 1.0900x; 1.0686x over previous
#include <cuda_runtime.h>
#include <math.h>

#define D 2048
#define SQ 2048
#define NB 8
#define NH 16
#define NL 2
#define DC 4096
#define IM 16384
#define PADID 50257
#define EPSLN 1e-5f
#define NLB (NL*NB)

typedef unsigned long long u64;
__device__ __forceinline__ u64 pk2(float x,float y){u64 r;asm("mov.b64 %0,{%1,%2};":"=l"(r):"f"(x),"f"(y));return r;}
__device__ __forceinline__ void fma2(u64&d,u64 a,u64 b){asm("fma.rn.f32x2 %0,%1,%2,%0;":"+l"(d):"l"(a),"l"(b));}
__device__ __forceinline__ void add2(u64&d,u64 a){asm("add.rn.f32x2 %0,%1,%0;":"+l"(d):"l"(a));}
__device__ __forceinline__ float2 up2(u64 v){float2 r;asm("mov.b64 {%0,%1},%2;":"=f"(r.x),"=f"(r.y):"l"(v));return r;}

__device__ float g_lnlast[NL*NB*D];
__device__ float g_qp[16*NL*NB*D];
__device__ float g_q[NL*NB*D];
__device__ float g_r[NL*NB*D*NH];
__device__ float g_t1[NLB*NH];
__device__ float g_t2[NLB*NH];
__device__ float g_dgp[4*NLB*NH*SQ];
__device__ float g_sump[4*NLB*SQ];
__device__ float g_ssqp[4*NLB*SQ];
__device__ float g_wt[NLB*NH*SQ];
__device__ float g_W0[NLB*NH];
__device__ float g_cp[4*NLB*NH*D];
__device__ float g_ofp[8*NLB*D];
__device__ float g_aop[16*NLB*D];
__device__ float g_hcat[NB*DC];
__device__ float g_z1p[16*NB*IM];
__device__ float g_z1[NB*IM];
__device__ float g_m2p[64*NB*DC];
__device__ float g_hfin[NB*DC];

#define FMA16(A,X,Q0,Q1,Q2,Q3) do{ float _x=(X); \
  A[0]+=_x*Q0.x;A[1]+=_x*Q0.y;A[2]+=_x*Q0.z;A[3]+=_x*Q0.w; \
  A[4]+=_x*Q1.x;A[5]+=_x*Q1.y;A[6]+=_x*Q1.z;A[7]+=_x*Q1.w; \
  A[8]+=_x*Q2.x;A[9]+=_x*Q2.y;A[10]+=_x*Q2.z;A[11]+=_x*Q2.w; \
  A[12]+=_x*Q3.x;A[13]+=_x*Q3.y;A[14]+=_x*Q3.z;A[15]+=_x*Q3.w; }while(0)

#define FMA8(A,W,Q0,Q1) do{ float _w=(W); \
  A[0]+=Q0.x*_w;A[1]+=Q0.y*_w;A[2]+=Q0.z*_w;A[3]+=Q0.w*_w; \
  A[4]+=Q1.x*_w;A[5]+=Q1.y*_w;A[6]+=Q1.z*_w;A[7]+=Q1.w*_w; }while(0)

// ---------- fused: idx scan + normalized last-token row ----------
__global__ void k_lnidx(const int* __restrict__ ids,
                        const float* __restrict__ hs0,const float* __restrict__ hs1,
                        const float* __restrict__ lng,const float* __restrict__ lnb){
  int b=blockIdx.x, l=blockIdx.y, t=threadIdx.x;
  int best=-1;
  for(int s=t;s<SQ;s+=256) if(ids[b*SQ+s]!=PADID) best=s;
  __shared__ int smi[256]; smi[t]=best; __syncthreads();
  for(int o=128;o;o>>=1){ if(t<o) smi[t]=max(smi[t],smi[t+o]); __syncthreads(); }
  int idx=smi[0]<0?0:smi[0];
  const float* x=(l?hs1:hs0)+((size_t)b*SQ+idx)*D;
  float xv[8],s1=0.f,s2=0.f;
#pragma unroll
  for(int k=0;k<8;k++){ float v=x[t+k*256]; xv[k]=v; s1+=v; s2+=v*v; }
  __shared__ float sa[256],sb[256];
  sa[t]=s1; sb[t]=s2; __syncthreads();
  for(int o=128;o;o>>=1){ if(t<o){ sa[t]+=sa[t+o]; sb[t]+=sb[t+o]; } __syncthreads(); }
  float m=sa[0]*(1.f/D), rs=rsqrtf(sb[0]*(1.f/D)-m*m+EPSLN);
  float* out=g_lnlast+(l*NB+b)*D;
#pragma unroll
  for(int k=0;k<8;k++){ int i=t+k*256; out[i]=(xv[k]-m)*rs*lng[l*D+i]+lnb[l*D+i]; }
}

// ---------- q = lnlast @ Wq (split-i partials) ----------
__global__ void k_q(const float* __restrict__ Wq){
  int t=threadIdx.x, n=blockIdx.x*256+t, sp=blockIdx.y, l=blockIdx.z;
  __shared__ float sln[128*NB];
  for(int idx=t;idx<128*NB;idx+=256){ int i=idx>>3,b=idx&7; sln[idx]=g_lnlast[(l*NB+b)*D+sp*128+i]; }
  __syncthreads();
  const float* W=Wq+(size_t)l*D*D+(size_t)sp*128*D+n;
  float acc[NB]={0};
#pragma unroll 8
  for(int i=0;i<128;i++){
    float w=W[(size_t)i*D];
    float4 l0=*(const float4*)&sln[i*8], l1=*(const float4*)&sln[i*8+4];
    FMA8(acc,w,l0,l1);
  }
#pragma unroll
  for(int b=0;b<NB;b++) g_qp[(size_t)((sp*NL+l)*NB+b)*D+n]=acc[b];
}
__global__ void k_qred(){
  int idx=blockIdx.x*256+threadIdx.x; if(idx>=NL*NB*D) return;
  float s=0;
#pragma unroll
  for(int sp=0;sp<16;sp++) s+=g_qp[(size_t)sp*NL*NB*D+idx];
  g_q[idx]=s;
}

// ---------- r[lb,i,h] = Wk[i,hslice] . q[hslice] ----------
__global__ void k_r(const float* __restrict__ Wk){
  int warp=threadIdx.x>>5, lane=threadIdx.x&31, l=blockIdx.y;
  int pair=blockIdx.x*8+warp, i=pair>>4, h=pair&15;
  float4 wv=*(const float4*)&Wk[(size_t)l*D*D+(size_t)i*D+h*128+lane*4];
  float a[NB];
#pragma unroll
  for(int b=0;b<NB;b++){
    float4 qv=*(const float4*)&g_q[(l*NB+b)*D+h*128+lane*4];
    a[b]=wv.x*qv.x+wv.y*qv.y+wv.z*qv.z+wv.w*qv.w;
  }
#pragma unroll
  for(int b=0;b<NB;b++)
    for(int o=16;o;o>>=1) a[b]+=__shfl_down_sync(0xffffffffu,a[b],o);
  if(lane==0){
#pragma unroll
    for(int b=0;b<NB;b++) g_r[((size_t)(l*NB+b)*D+i)*NH+h]=a[b];
  }
}

// ---------- t1 = sum_i g r ; t2 = sum_i b r ----------
__global__ void k_t(const float* __restrict__ lng,const float* __restrict__ lnb){
  int lb=blockIdx.x, t=threadIdx.x, l=lb>>3;
  float a1[16]={0},a2[16]={0};
  for(int i=t;i<D;i+=256){
    float g=lng[l*D+i], bb=lnb[l*D+i];
    const float4* rp=(const float4*)(g_r+((size_t)lb*D+i)*NH);
    float4 r0=rp[0],r1=rp[1],r2=rp[2],r3=rp[3];
    FMA16(a1,g,r0,r1,r2,r3); FMA16(a2,bb,r0,r1,r2,r3);
  }
#pragma unroll
  for(int h=0;h<16;h++)
    for(int o=16;o;o>>=1){ a1[h]+=__shfl_down_sync(~0u,a1[h],o); a2[h]+=__shfl_down_sync(~0u,a2[h],o); }
  __shared__ float s1[8][16],s2[8][16];
  int w=t>>5;
  if((t&31)==0){ for(int h=0;h<16;h++){ s1[w][h]=a1[h]; s2[w][h]=a2[h]; } }
  __syncthreads();
  if(t<16){ float x=0,y=0; for(int w2=0;w2<8;w2++){ x+=s1[w2][t]; y+=s2[w2][t]; }
    g_t1[lb*NH+t]=x; g_t2[lb*NH+t]=y; }
}

// ---------- pass1: dg[s,h], sum[s], ssq[s] with packed f32x2 FMA ----------
__global__ void __launch_bounds__(256) k_pass1(const float* __restrict__ hs0,const float* __restrict__ hs1,
                        const float* __restrict__ lng){
  __shared__ float rs[512*16];
  int t=threadIdx.x, sp=blockIdx.x, rg=blockIdx.y, lb=blockIdx.z;
  int l=lb>>3, b=lb&7, kb=sp*512;
  const float* x=(l?hs1:hs0)+(size_t)b*SQ*D;
  const float4* rsrc=(const float4*)(g_r+((size_t)lb*D+kb)*NH);
  float4* rs4=(float4*)rs;
  for(int idx=t;idx<2048;idx+=256){
    float g=lng[l*D+kb+(idx>>2)];
    float4 v=rsrc[idx]; v.x*=g; v.y*=g; v.z*=g; v.w*=g; rs4[idx]=v;
  }
  __syncthreads();
  int r0=rg*512+t, r1=r0+256;
  u64 a0[8]={},a1[8]={},s2=0,q2=0;
  const float4* x0=(const float4*)(x+(size_t)r0*D+kb);
  const float4* x1=(const float4*)(x+(size_t)r1*D+kb);
  for(int kk=0;kk<512;kk+=16){
    float4 xa[4],xb[4];
#pragma unroll
    for(int j=0;j<4;j++){ xa[j]=x0[(kk>>2)+j]; xb[j]=x1[(kk>>2)+j]; }
    const float* ua=(const float*)xa; const float* vb=(const float*)xb;
#pragma unroll
    for(int j=0;j<16;j++){
      float u=ua[j], v=vb[j];
      u64 uu=pk2(u,u), vv=pk2(v,v), uv=pk2(u,v);
      add2(s2,uv); fma2(q2,uv,uv);
      const ulonglong2* qp=(const ulonglong2*)(rs+(kk+j)*16);
      ulonglong2 qA=qp[0],qB=qp[1],qC=qp[2],qD=qp[3];
      fma2(a0[0],uu,qA.x); fma2(a0[1],uu,qA.y);
      fma2(a0[2],uu,qB.x); fma2(a0[3],uu,qB.y);
      fma2(a0[4],uu,qC.x); fma2(a0[5],uu,qC.y);
      fma2(a0[6],uu,qD.x); fma2(a0[7],uu,qD.y);
      fma2(a1[0],vv,qA.x); fma2(a1[1],vv,qA.y);
      fma2(a1[2],vv,qB.x); fma2(a1[3],vv,qB.y);
      fma2(a1[4],vv,qC.x); fma2(a1[5],vv,qC.y);
      fma2(a1[6],vv,qD.x); fma2(a1[7],vv,qD.y);
    }
  }
  size_t base=(size_t)((sp*NLB+lb)*NH)*SQ;
#pragma unroll
  for(int k=0;k<8;k++){
    float2 f0=up2(a0[k]), f1=up2(a1[k]);
    g_dgp[base+(size_t)(2*k)*SQ+r0]=f0.x; g_dgp[base+(size_t)(2*k+1)*SQ+r0]=f0.y;
    g_dgp[base+(size_t)(2*k)*SQ+r1]=f1.x; g_dgp[base+(size_t)(2*k+1)*SQ+r1]=f1.y;
  }
  float2 sv=up2(s2), qv=up2(q2);
  g_sump[(sp*NLB+lb)*SQ+r0]=sv.x; g_sump[(sp*NLB+lb)*SQ+r1]=sv.y;
  g_ssqp[(sp*NLB+lb)*SQ+r0]=qv.x; g_ssqp[(sp*NLB+lb)*SQ+r1]=qv.y;
}

// ---------- scores + softmax -> wt = w*rstd, W0 = sum wt*m ----------
__global__ void k_soft(){
  int h=blockIdx.x, lb=blockIdx.y, t=threadIdx.x;
  float t1=g_t1[lb*NH+h], t2=g_t2[lb*NH+h];
  float sc[8],mm[8],rr[8];
#pragma unroll
  for(int k=0;k<8;k++){
    int s=t+k*256; float su=0,sq=0,dg=0;
#pragma unroll
    for(int sp=0;sp<4;sp++){
      su+=g_sump[(sp*NLB+lb)*SQ+s]; sq+=g_ssqp[(sp*NLB+lb)*SQ+s];
      dg+=g_dgp[(size_t)((sp*NLB+lb)*NH+h)*SQ+s];
    }
    float m=su*(1.f/D), var=sq*(1.f/D)-m*m, rs=rsqrtf(var+EPSLN);
    mm[k]=m; rr[k]=rs; sc[k]=rs*(dg-m*t1)+t2;
  }
  __shared__ float sm[256];
  float mx=sc[0];
#pragma unroll
  for(int k=1;k<8;k++) mx=fmaxf(mx,sc[k]);
  sm[t]=mx; __syncthreads();
  for(int o=128;o;o>>=1){ if(t<o) sm[t]=fmaxf(sm[t],sm[t+o]); __syncthreads(); }
  mx=sm[0]; __syncthreads();
  float e[8],es=0;
#pragma unroll
  for(int k=0;k<8;k++){ e[k]=expf(sc[k]-mx); es+=e[k]; }
  sm[t]=es; __syncthreads();
  for(int o=128;o;o>>=1){ if(t<o) sm[t]+=sm[t+o]; __syncthreads(); }
  float inv=1.f/sm[0]; __syncthreads();
  float w0=0;
#pragma unroll
  for(int k=0;k<8;k++){
    float wt=e[k]*inv*rr[k];
    g_wt[(size_t)(lb*NH+h)*SQ+t+k*256]=wt; w0+=wt*mm[k];
  }
  sm[t]=w0; __syncthreads();
  for(int o=128;o;o>>=1){ if(t<o) sm[t]+=sm[t+o]; __syncthreads(); }
  if(t==0) g_W0[lb*NH+h]=sm[0];
}

// ---------- pass2: craw[h,d] = sum_s wt[h,s] x[s,d] with packed f32x2 FMA ----------
__global__ void __launch_bounds__(256) k_pass2(const float* __restrict__ hs0,const float* __restrict__ hs1){
  __shared__ float swt[512*16];
  int t=threadIdx.x, sp=blockIdx.x, cg=blockIdx.y, lb=blockIdx.z;
  int l=lb>>3, b=lb&7, sb=sp*512;
  for(int h=0;h<16;h++)
    for(int s=t;s<512;s+=256) swt[s*16+h]=g_wt[(size_t)(lb*NH+h)*SQ+sb+s];
  __syncthreads();
  const float* x=(l?hs1:hs0)+(size_t)b*SQ*D;
  int c=cg*512+t*2;
  u64 a0[8]={},a1[8]={};
  for(int s=0;s<512;s+=8){
    float2 xv[8];
#pragma unroll
    for(int j=0;j<8;j++) xv[j]=*(const float2*)&x[(size_t)(sb+s+j)*D+c];
#pragma unroll
    for(int j=0;j<8;j++){
      u64 uu=pk2(xv[j].x,xv[j].x), vv=pk2(xv[j].y,xv[j].y);
      const ulonglong2* qp=(const ulonglong2*)(swt+(s+j)*16);
      ulonglong2 qA=qp[0],qB=qp[1],qC=qp[2],qD=qp[3];
      fma2(a0[0],uu,qA.x); fma2(a0[1],uu,qA.y);
      fma2(a0[2],uu,qB.x); fma2(a0[3],uu,qB.y);
      fma2(a0[4],uu,qC.x); fma2(a0[5],uu,qC.y);
      fma2(a0[6],uu,qD.x); fma2(a0[7],uu,qD.y);
      fma2(a1[0],vv,qA.x); fma2(a1[1],vv,qA.y);
      fma2(a1[2],vv,qB.x); fma2(a1[3],vv,qB.y);
      fma2(a1[4],vv,qC.x); fma2(a1[5],vv,qC.y);
      fma2(a1[6],vv,qD.x); fma2(a1[7],vv,qD.y);
    }
  }
  size_t base=(size_t)((sp*NLB+lb)*NH)*D;
#pragma unroll
  for(int k=0;k<8;k++){
    float2 f0=up2(a0[k]), f1=up2(a1[k]);
    float2 stA; stA.x=f0.x; stA.y=f1.x;
    float2 stB; stB.x=f0.y; stB.y=f1.y;
    *(float2*)&g_cp[base+(size_t)(2*k)*D+c]=stA;
    *(float2*)&g_cp[base+(size_t)(2*k+1)*D+c]=stB;
  }
}

// ---------- oflat = c @ Wv  (cred fused into smem build) ----------
__global__ void k_of(const float* __restrict__ Wv,
                     const float* __restrict__ lng,const float* __restrict__ lnb){
  __shared__ float sc[256*8];
  int t=threadIdx.x, h=blockIdx.x, sp=blockIdx.y, l=blockIdx.z, db=sp*256;
  for(int idx=t;idx<256*8;idx+=128){
    int d=idx>>3, b=idx&7, lb=l*8+b;
    float s=0;
#pragma unroll
    for(int p=0;p<4;p++) s+=g_cp[(size_t)((p*NLB+lb)*NH+h)*D+db+d];
    sc[idx]=lng[l*D+db+d]*(s-g_W0[lb*NH+h])+lnb[l*D+db+d];
  }
  __syncthreads();
  const float* W=Wv+(size_t)l*D*D+(size_t)db*D+h*128+t;
  float acc[NB]={0};
#pragma unroll 8
  for(int d=0;d<256;d++){
    float w=W[(size_t)d*D];
    float4 c0=*(const float4*)&sc[d*8],c1=*(const float4*)&sc[d*8+4];
    FMA8(acc,w,c0,c1);
  }
#pragma unroll
  for(int b=0;b<NB;b++) g_ofp[(size_t)((sp*NL+l)*NB+b)*D+h*128+t]=acc[b];
}

// ---------- attnout = of @ Wo -> hcat partials (ofred fused into smem build) ----------
__global__ void k_ao(const float* __restrict__ Wo){
  __shared__ float sof[128*8];
  int t=threadIdx.x, cb=blockIdx.x, sp=blockIdx.y, l=blockIdx.z, mb=sp*128, n=cb*256+t;
  for(int idx=t;idx<128*8;idx+=256){
    int m=idx>>3, b=idx&7;
    float s=0;
#pragma unroll
    for(int p=0;p<8;p++) s+=g_ofp[(size_t)((p*NL+l)*NB+b)*D+mb+m];
    sof[idx]=s;
  }
  __syncthreads();
  const float* W=Wo+(size_t)l*D*D+(size_t)mb*D+n;
  float acc[NB]={0};
#pragma unroll 8
  for(int m=0;m<128;m++){
    float w=W[(size_t)m*D];
    float4 o0=*(const float4*)&sof[m*8],o1=*(const float4*)&sof[m*8+4];
    FMA8(acc,w,o0,o1);
  }
#pragma unroll
  for(int b=0;b<NB;b++) g_aop[(size_t)((sp*NL+l)*NB+b)*D+n]=acc[b];
}
__global__ void k_aored(const float* __restrict__ bo){
  int idx=blockIdx.x*256+threadIdx.x; if(idx>=NLB*D) return;
  int n=idx&(D-1), lb=idx>>11, l=lb>>3, b=lb&7;
  float s=0;
#pragma unroll
  for(int sp=0;sp<16;sp++) s+=g_aop[(size_t)sp*NLB*D+idx];
  g_hcat[b*DC+l*D+n]=s+bo[l*D+n];
}

// ---------- MLP layer 1 (f32x2 packed) ----------
__global__ void k_m1(const float* __restrict__ W1){
  __shared__ float sh[256*8];
  int t=threadIdx.x, p=blockIdx.x*1024+t*4, cb=blockIdx.y*256;
  for(int idx=t;idx<256*8;idx+=256){ int c=idx>>3,b=idx&7; sh[idx]=g_hcat[b*DC+cb+c]; }
  __syncthreads();
  const float* W=W1+(size_t)cb*IM+p;
  u64 accA[8]={},accB[8]={};
#pragma unroll 8
  for(int c=0;c<256;c++){
    ulonglong2 w2=*(const ulonglong2*)&W[(size_t)c*IM];
    float4 h0=*(const float4*)&sh[c*8], h1=*(const float4*)&sh[c*8+4];
    float hb[8]={h0.x,h0.y,h0.z,h0.w,h1.x,h1.y,h1.z,h1.w};
#pragma unroll
    for(int b=0;b<8;b++){
      u64 hh=pk2(hb[b],hb[b]);
      fma2(accA[b],hh,w2.x); fma2(accB[b],hh,w2.y);
    }
  }
#pragma unroll
  for(int b=0;b<8;b++){
    float2 fa=up2(accA[b]), fb=up2(accB[b]);
    float4 st; st.x=fa.x; st.y=fa.y; st.z=fb.x; st.w=fb.y;
    *(float4*)&g_z1p[(size_t)(blockIdx.y*NB+b)*IM+p]=st;
  }
}
__global__ void k_z1red(const float* __restrict__ b1){
  int idx=blockIdx.x*256+threadIdx.x; if(idx>=NB*IM) return;
  int p=idx&(IM-1);
  float s=b1[p];
#pragma unroll
  for(int sp=0;sp<16;sp++) s+=g_z1p[(size_t)sp*NB*IM+idx];
  g_z1[idx]=0.5f*s*(1.0f+erff(s*0.70710678118654752f));
}

// ---------- MLP layer 2 (f32x2 packed) ----------
__global__ void k_m2(const float* __restrict__ W2){
  __shared__ float sz[256*8];
  int t=threadIdx.x, c=blockIdx.x*1024+t*4, pb=blockIdx.y*256;
  for(int idx=t;idx<256*8;idx+=256){ int pp=idx>>3,b=idx&7; sz[idx]=g_z1[b*IM+pb+pp]; }
  __syncthreads();
  const float* W=W2+(size_t)pb*DC+c;
  u64 accA[8]={},accB[8]={};
#pragma unroll 8
  for(int pp=0;pp<256;pp++){
    ulonglong2 w2=*(const ulonglong2*)&W[(size_t)pp*DC];
    float4 z0=*(const float4*)&sz[pp*8], z1v=*(const float4*)&sz[pp*8+4];
    float zb[8]={z0.x,z0.y,z0.z,z0.w,z1v.x,z1v.y,z1v.z,z1v.w};
#pragma unroll
    for(int b=0;b<8;b++){
      u64 zz=pk2(zb[b],zb[b]);
      fma2(accA[b],zz,w2.x); fma2(accB[b],zz,w2.y);
    }
  }
#pragma unroll
  for(int b=0;b<8;b++){
    float2 fa=up2(accA[b]), fb=up2(accB[b]);
    float4 st; st.x=fa.x; st.y=fa.y; st.z=fb.x; st.w=fb.y;
    *(float4*)&g_m2p[(size_t)(blockIdx.y*NB+b)*DC+c]=st;
  }
}
__global__ void k_m2red(const float* __restrict__ b2){
  int idx=blockIdx.x*256+threadIdx.x; if(idx>=NB*DC) return;
  int c=idx&(DC-1);
  float s=b2[c];
#pragma unroll
  for(int sp=0;sp<64;sp++) s+=g_m2p[(size_t)sp*NB*DC+idx];
  g_hfin[idx]=g_hcat[idx]+s;
}

// ---------- final logits ----------
__global__ void k_out(const float* __restrict__ Wl,const float* __restrict__ bl,
                      float* __restrict__ out){
  int b=blockIdx.x, t=threadIdx.x;
  float a0=0,a1=0;
  for(int c=t;c<DC;c+=256){
    float h=g_hfin[b*DC+c];
    a0+=h*Wl[c*2]; a1+=h*Wl[c*2+1];
  }
  __shared__ float s0[256],s1[256];
  s0[t]=a0; s1[t]=a1; __syncthreads();
  for(int o=128;o;o>>=1){ if(t<o){ s0[t]+=s0[t+o]; s1[t]+=s1[t+o]; } __syncthreads(); }
  if(t==0){ out[b*2]=s0[0]+bl[0]; out[b*2+1]=s1[0]+bl[1]; }
}

extern "C" void kernel_launch(void* const* d_in, const int* in_sizes, int n_in,
                              void* d_out, int out_size){
  const float* hs0=(const float*)d_in[0];
  const float* hs1=(const float*)d_in[1];
  const int*   ids=(const int*)d_in[2];
  const float* lng=(const float*)d_in[3];
  const float* lnb=(const float*)d_in[4];
  const float* Wq =(const float*)d_in[5];
  const float* Wk =(const float*)d_in[6];
  const float* Wv =(const float*)d_in[7];
  const float* Wo =(const float*)d_in[8];
  const float* bo =(const float*)d_in[9];
  const float* W1 =(const float*)d_in[10];
  const float* b1 =(const float*)d_in[11];
  const float* W2 =(const float*)d_in[12];
  const float* b2 =(const float*)d_in[13];
  const float* Wl =(const float*)d_in[14];
  const float* bl =(const float*)d_in[15];
  float* out=(float*)d_out;

  k_lnidx<<<dim3(NB,NL),256>>>(ids,hs0,hs1,lng,lnb);
  k_q<<<dim3(8,16,NL),256>>>(Wq);
  k_qred<<<(NL*NB*D)/256,256>>>();
  k_r<<<dim3(D*NH/8,NL),256>>>(Wk);
  k_t<<<NLB,256>>>(lng,lnb);
  k_pass1<<<dim3(4,4,NLB),256>>>(hs0,hs1,lng);
  k_soft<<<dim3(NH,NLB),256>>>();
  k_pass2<<<dim3(4,4,NLB),256>>>(hs0,hs1);
  k_of<<<dim3(16,8,NL),128>>>(Wv,lng,lnb);
  k_ao<<<dim3(8,16,NL),256>>>(Wo);
  k_aored<<<(NLB*D)/256,256>>>(bo);
  k_m1<<<dim3(IM/1024,16),256>>>(W1);
  k_z1red<<<(NB*IM)/256,256>>>(b1);
  k_m2<<<dim3(DC/1024,64),256>>>(W2);
  k_m2red<<<(NB*DC)/256,256>>>(b2);
  k_out<<<NB,256>>>(Wl,bl,out);
}